// round 7
// baseline (speedup 1.0000x reference)
#include <cuda_runtime.h>

#define NPTS 8192
#define CIN  256
#define NSAMP 16
#define HDIM 32
#define GRES 8
#define CELLS (GRES * GRES * GRES)
#define CELLH 0.125f

// ---------------- scratch (device globals; no allocation) ----------------
__device__ float4 g_p4[NPTS];               // (x, y, z, |p|^2)
__device__ int    g_idx[NPTS * NSAMP];
__device__ float  g_xq[NPTS * CIN];
__device__ float  g_xk[NPTS * CIN];
__device__ float  g_xv[NPTS * CIN];
__device__ float  g_w2t[HDIM * HDIM];       // w_l2_w transposed: [h][k]
__device__ float  g_bn1s[CIN], g_bn1h[CIN];
__device__ float  g_bn2s[HDIM], g_bn2h[HDIM];
// grid structures
__device__ int    g_cellCnt[CELLS];         // counts, then reused as scatter cursor
__device__ int    g_cellStart[CELLS + 1];
__device__ float4 g_sp[NPTS];               // points sorted by cell
__device__ int    g_sidx[NPTS];             // original index of sorted point

__device__ __forceinline__ int cellCoord(float v) {
    int c = (int)(v * (float)GRES);
    return min(GRES - 1, max(0, c));
}

// ---------------- setup: pack points, zero cell counts, prep weights ----------------
__global__ void setup_kernel(const float* __restrict__ p,
                             const float* __restrict__ w_l2_w,
                             const float* __restrict__ g1, const float* __restrict__ b1,
                             const float* __restrict__ m1, const float* __restrict__ v1,
                             const float* __restrict__ g2, const float* __restrict__ b2,
                             const float* __restrict__ m2, const float* __restrict__ v2) {
    int i = blockIdx.x * 256 + threadIdx.x;
    if (i < NPTS) {
        float x = p[3 * i], y = p[3 * i + 1], z = p[3 * i + 2];
        g_p4[i] = make_float4(x, y, z, fmaf(z, z, fmaf(y, y, x * x)));
    }
    if (i < CELLS) g_cellCnt[i] = 0;
    if (blockIdx.x == 31) {
        int tid = threadIdx.x;
        for (int e = tid; e < HDIM * HDIM; e += 256) {
            int h = e >> 5, k = e & 31;
            g_w2t[e] = w_l2_w[k * HDIM + h];
        }
        if (tid < CIN) {
            float s = g1[tid] * rsqrtf(v1[tid] + 1e-5f);
            g_bn1s[tid] = s;
            g_bn1h[tid] = b1[tid] - m1[tid] * s;
        }
        if (tid < HDIM) {
            float s = g2[tid] * rsqrtf(v2[tid] + 1e-5f);
            g_bn2s[tid] = s;
            g_bn2h[tid] = b2[tid] - m2[tid] * s;
        }
    }
}

// ---------------- count points per cell ----------------
__global__ void count_kernel() {
    int i = blockIdx.x * 256 + threadIdx.x;
    if (i < NPTS) {
        float4 pt = g_p4[i];
        int c = cellCoord(pt.x) + (cellCoord(pt.y) << 3) + (cellCoord(pt.z) << 6);
        atomicAdd(&g_cellCnt[c], 1);
    }
}

// ---------------- single-block scan + scatter ----------------
__global__ __launch_bounds__(CELLS) void scan_scatter_kernel() {
    __shared__ int s[CELLS];
    int tid = threadIdx.x;
    int cnt = g_cellCnt[tid];
    s[tid] = cnt;
    __syncthreads();
    // Hillis-Steele inclusive scan
    for (int off = 1; off < CELLS; off <<= 1) {
        int v = 0;
        if (tid >= off) v = s[tid - off];
        __syncthreads();
        if (tid >= off) s[tid] += v;
        __syncthreads();
    }
    int start = s[tid] - cnt;
    g_cellStart[tid] = start;
    if (tid == CELLS - 1) g_cellStart[CELLS] = s[tid];
    g_cellCnt[tid] = start;     // reuse as cursor
    __syncthreads();
    // scatter (single block, grid-stride over points)
    for (int i = tid; i < NPTS; i += CELLS) {
        float4 pt = g_p4[i];
        int c = cellCoord(pt.x) + (cellCoord(pt.y) << 3) + (cellCoord(pt.z) << 6);
        int pos = atomicAdd(&g_cellCnt[c], 1);
        g_sp[pos] = pt;
        g_sidx[pos] = i;
    }
}

// ---------------- grid KNN query: thread per (spatially sorted) query ----------------
// Exact top-16 by lexicographic (distance, index) == jax.lax.top_k(-d) semantics.
__global__ __launch_bounds__(128) void knn_query() {
    int t = blockIdx.x * 128 + threadIdx.x;
    float4 qp = g_sp[t];
    int orig = g_sidx[t];
    float qx = qp.x, qy = qp.y, qz = qp.z, qsq = qp.w;
    int cx = cellCoord(qx), cy = cellCoord(qy), cz = cellCoord(qz);

    const float FINF = 3.402823466e+38f;
    float ld_[16];
    int   li_[16];
#pragma unroll
    for (int k = 0; k < 16; ++k) { ld_[k] = FINF; li_[k] = 0x7fffffff; }

#define SCAN_CELL(CX, CY, CZ)                                                   \
    {                                                                           \
        int cc = (CX) + ((CY) << 3) + ((CZ) << 6);                              \
        int s0 = g_cellStart[cc], s1 = g_cellStart[cc + 1];                     \
        for (int j = s0; j < s1; ++j) {                                         \
            float4 tp = g_sp[j];                                                \
            float dot = fmaf(qz, tp.z, fmaf(qy, tp.y, qx * tp.x));              \
            float d = fmaf(-2.f, dot, qsq + tp.w);                              \
            int idx = g_sidx[j];                                                \
            if (d < ld_[15] || (d == ld_[15] && idx < li_[15])) {               \
                ld_[15] = d; li_[15] = idx;                                     \
                _Pragma("unroll")                                               \
                for (int m = 15; m > 0; --m) {                                  \
                    bool sw = (ld_[m] < ld_[m - 1]) ||                          \
                              (ld_[m] == ld_[m - 1] && li_[m] < li_[m - 1]);    \
                    if (sw) {                                                   \
                        float td = ld_[m]; ld_[m] = ld_[m - 1]; ld_[m - 1] = td;\
                        int ti = li_[m]; li_[m] = li_[m - 1]; li_[m - 1] = ti;  \
                    }                                                           \
                }                                                               \
            }                                                                   \
        }                                                                       \
    }

    // initial box: Chebyshev distance <= 1
    {
        int z0 = max(0, cz - 1), z1 = min(GRES - 1, cz + 1);
        int y0 = max(0, cy - 1), y1 = min(GRES - 1, cy + 1);
        int x0 = max(0, cx - 1), x1 = min(GRES - 1, cx + 1);
        for (int z = z0; z <= z1; ++z)
            for (int y = y0; y <= y1; ++y)
                for (int x = x0; x <= x1; ++x)
                    SCAN_CELL(x, y, z)
    }

    int R = 1;
    while (true) {
        bool have16 = (li_[15] != 0x7fffffff);
        float rb = (float)R * CELLH;
        // all unprocessed points are geometrically >= R*h away; margin covers
        // the fp discrepancy of the qsq+psq-2*dot formula vs true distance.
        if (have16 && rb * rb > ld_[15] * 1.00001f + 1e-6f) break;
        if (R >= GRES) break;
        ++R;
        // process shell Chebyshev == R
        for (int dz = -R; dz <= R; ++dz) {
            int z = cz + dz;
            if (z < 0 || z > GRES - 1) continue;
            int adz = dz < 0 ? -dz : dz;
            for (int dy = -R; dy <= R; ++dy) {
                int y = cy + dy;
                if (y < 0 || y > GRES - 1) continue;
                int ady = dy < 0 ? -dy : dy;
                bool faceZY = (adz == R) || (ady == R);
                for (int dx = -R; dx <= R; ++dx) {
                    int x = cx + dx;
                    if (x < 0 || x > GRES - 1) continue;
                    int adx = dx < 0 ? -dx : dx;
                    if (!faceZY && adx != R) continue;
                    SCAN_CELL(x, y, z)
                }
            }
        }
    }
#undef SCAN_CELL

#pragma unroll
    for (int k = 0; k < 16; ++k) g_idx[orig * NSAMP + k] = li_[k];
}

// ---------------- QKV SGEMM: 128x128x8 tiles, 8x8/thread, double buffered ----------------
__global__ __launch_bounds__(256) void qkv_gemm(
    const float* __restrict__ x,
    const float* __restrict__ w_q, const float* __restrict__ b_q,
    const float* __restrict__ w_k, const float* __restrict__ b_k,
    const float* __restrict__ w_v, const float* __restrict__ b_v) {

    const int BM = 128, BN = 128, BK = 8, TM = 8, TN = 8;
    __shared__ float As[2][BK * BM];  // transposed
    __shared__ float Bs[2][BK * BN];

    const float* W; const float* bias; float* O;
    if (blockIdx.z == 0)      { W = w_q; bias = b_q; O = g_xq; }
    else if (blockIdx.z == 1) { W = w_k; bias = b_k; O = g_xk; }
    else                      { W = w_v; bias = b_v; O = g_xv; }

    int tid = threadIdx.x;
    int cRow = blockIdx.y, cCol = blockIdx.x;

    int innerRowA = tid >> 1, innerColA = tid & 1;          // 128 rows x 2 float4
    int innerRowB = tid >> 5, innerColB = tid & 31;         // 8 rows x 32 float4
    int threadCol = tid & 15, threadRow = tid >> 4;

    const float* Aptr = &x[(cRow * BM + innerRowA) * CIN + innerColA * 4];
    const float* Bptr = &W[innerRowB * CIN + cCol * BN + innerColB * 4];

    float acc[TM][TN];
#pragma unroll
    for (int i = 0; i < TM; ++i)
#pragma unroll
        for (int j = 0; j < TN; ++j) acc[i][j] = 0.f;

    float regM[TM], regN[TN];

    // prologue: tile 0 into buffer 0
    {
        float4 tA = *reinterpret_cast<const float4*>(Aptr);
        float4 tB = *reinterpret_cast<const float4*>(Bptr);
        As[0][(innerColA * 4 + 0) * BM + innerRowA] = tA.x;
        As[0][(innerColA * 4 + 1) * BM + innerRowA] = tA.y;
        As[0][(innerColA * 4 + 2) * BM + innerRowA] = tA.z;
        As[0][(innerColA * 4 + 3) * BM + innerRowA] = tA.w;
        *reinterpret_cast<float4*>(&Bs[0][innerRowB * BN + innerColB * 4]) = tB;
    }
    __syncthreads();

    int buf = 0;
#pragma unroll 2
    for (int k0 = 0; k0 < CIN - BK; k0 += BK) {
        float4 nA = *reinterpret_cast<const float4*>(Aptr + k0 + BK);
        float4 nB = *reinterpret_cast<const float4*>(Bptr + (k0 + BK) * CIN);

#pragma unroll
        for (int k = 0; k < BK; ++k) {
#pragma unroll
            for (int i = 0; i < TM; i += 4)
                *reinterpret_cast<float4*>(&regM[i]) =
                    *reinterpret_cast<float4*>(&As[buf][k * BM + threadRow * TM + i]);
#pragma unroll
            for (int j = 0; j < TN; j += 4)
                *reinterpret_cast<float4*>(&regN[j]) =
                    *reinterpret_cast<float4*>(&Bs[buf][k * BN + threadCol * TN + j]);
#pragma unroll
            for (int i = 0; i < TM; ++i)
#pragma unroll
                for (int j = 0; j < TN; ++j)
                    acc[i][j] = fmaf(regM[i], regN[j], acc[i][j]);
        }

        int nb = buf ^ 1;
        As[nb][(innerColA * 4 + 0) * BM + innerRowA] = nA.x;
        As[nb][(innerColA * 4 + 1) * BM + innerRowA] = nA.y;
        As[nb][(innerColA * 4 + 2) * BM + innerRowA] = nA.z;
        As[nb][(innerColA * 4 + 3) * BM + innerRowA] = nA.w;
        *reinterpret_cast<float4*>(&Bs[nb][innerRowB * BN + innerColB * 4]) = nB;
        __syncthreads();
        buf = nb;
    }

    // last tile
#pragma unroll
    for (int k = 0; k < BK; ++k) {
#pragma unroll
        for (int i = 0; i < TM; i += 4)
            *reinterpret_cast<float4*>(&regM[i]) =
                *reinterpret_cast<float4*>(&As[buf][k * BM + threadRow * TM + i]);
#pragma unroll
        for (int j = 0; j < TN; j += 4)
            *reinterpret_cast<float4*>(&regN[j]) =
                *reinterpret_cast<float4*>(&Bs[buf][k * BN + threadCol * TN + j]);
#pragma unroll
        for (int i = 0; i < TM; ++i)
#pragma unroll
            for (int j = 0; j < TN; ++j)
                acc[i][j] = fmaf(regM[i], regN[j], acc[i][j]);
    }

    int col0 = cCol * BN + threadCol * TN;
    float breg[TN];
#pragma unroll
    for (int j = 0; j < TN; ++j) breg[j] = bias[col0 + j];

#pragma unroll
    for (int i = 0; i < TM; ++i) {
        int row = cRow * BM + threadRow * TM + i;
        float4 v0 = make_float4(acc[i][0] + breg[0], acc[i][1] + breg[1],
                                acc[i][2] + breg[2], acc[i][3] + breg[3]);
        float4 v1 = make_float4(acc[i][4] + breg[4], acc[i][5] + breg[5],
                                acc[i][6] + breg[6], acc[i][7] + breg[7]);
        *reinterpret_cast<float4*>(&O[row * CIN + col0])     = v0;
        *reinterpret_cast<float4*>(&O[row * CIN + col0 + 4]) = v1;
    }
}

// ---------------- fused per-point kernel ----------------
__global__ __launch_bounds__(256) void fused_kernel(
    const float* __restrict__ p,
    const float* __restrict__ p_w1, const float* __restrict__ p_b1,
    const float* __restrict__ p_bn_g, const float* __restrict__ p_bn_b,
    const float* __restrict__ p_bn_m, const float* __restrict__ p_bn_v,
    const float* __restrict__ p_w2, const float* __restrict__ p_b2,
    const float* __restrict__ w_l1_w, const float* __restrict__ w_l1_b,
    const float* __restrict__ w_l2_b,
    float* __restrict__ out) {

    __shared__ float s_xq[CIN];             // 1 KB
    __shared__ float s_pr[NSAMP * CIN];     // 16 KB
    __shared__ float s_a[NSAMP * CIN];      // 16 KB (reused as partials)
    __shared__ float s_u[NSAMP * HDIM];     // 2 KB
    __shared__ float s_w[NSAMP * 33];       // padded
    __shared__ int   s_idx[NSAMP];
    __shared__ float s_tv[NSAMP][3];
    __shared__ float s_pn[3];

    int n = blockIdx.x, tid = threadIdx.x, lane = tid & 31, warp = tid >> 5;

    if (tid < NSAMP) s_idx[tid] = g_idx[n * NSAMP + tid];
    if (tid < 3)     s_pn[tid] = p[n * 3 + tid];
    s_xq[tid] = g_xq[n * CIN + tid];
    __syncthreads();

    // pr hidden: Linear(3,3) -> BN -> ReLU, one thread per neighbor
    if (tid < NSAMP) {
        int j = s_idx[tid];
        float dx = p[j * 3]     - s_pn[0];
        float dy = p[j * 3 + 1] - s_pn[1];
        float dz = p[j * 3 + 2] - s_pn[2];
#pragma unroll
        for (int k = 0; k < 3; ++k) {
            float h = dx * p_w1[k] + dy * p_w1[3 + k] + dz * p_w1[6 + k] + p_b1[k];
            h = (h - p_bn_m[k]) * rsqrtf(p_bn_v[k] + 1e-5f) * p_bn_g[k] + p_bn_b[k];
            s_tv[tid][k] = fmaxf(h, 0.f);
        }
    }
    __syncthreads();

    // pr full (3->256) + gather xk + bn1/relu into s_a
    {
        float b1s = g_bn1s[tid], b1h = g_bn1h[tid];
        float xqv = s_xq[tid];
        float w20 = p_w2[tid], w21 = p_w2[256 + tid], w22 = p_w2[512 + tid];
        float pb2 = p_b2[tid];
#pragma unroll
        for (int r = 0; r < NSAMP; ++r) {
            float prv = fmaf(s_tv[r][2], w22, fmaf(s_tv[r][1], w21, fmaf(s_tv[r][0], w20, pb2)));
            s_pr[r * CIN + tid] = prv;
            float rqk = g_xk[s_idx[r] * CIN + tid] - xqv + prv;
            s_a[r * CIN + tid] = fmaxf(fmaf(rqk, b1s, b1h), 0.f);
        }
    }
    __syncthreads();

    // layer-1 matvec: warp owns 32 input channels (c = warp*32..+31), lane = output h.
    // w_l1_w read in original [c][h] layout -> coalesced LDG across lanes.
    float acc[NSAMP];
#pragma unroll
    for (int ns = 0; ns < NSAMP; ++ns) acc[ns] = 0.f;
    {
        int cbase = warp * 32;
#pragma unroll
        for (int g = 0; g < 8; ++g) {
            int c0 = cbase + g * 4;
            float wa = w_l1_w[(c0 + 0) * HDIM + lane];
            float wb = w_l1_w[(c0 + 1) * HDIM + lane];
            float wc = w_l1_w[(c0 + 2) * HDIM + lane];
            float wd = w_l1_w[(c0 + 3) * HDIM + lane];
#pragma unroll
            for (int ns = 0; ns < NSAMP; ++ns) {
                float4 av = *reinterpret_cast<const float4*>(&s_a[ns * CIN + c0]);
                acc[ns] = fmaf(av.x, wa, acc[ns]);
                acc[ns] = fmaf(av.y, wb, acc[ns]);
                acc[ns] = fmaf(av.z, wc, acc[ns]);
                acc[ns] = fmaf(av.w, wd, acc[ns]);
            }
        }
    }
    __syncthreads();   // all reads of s_a done before reuse as partial buffer

    float* s_part = s_a;   // 8*16*32 = 4096 floats, fits exactly
#pragma unroll
    for (int ns = 0; ns < NSAMP; ++ns)
        s_part[(warp * NSAMP + ns) * 32 + lane] = acc[ns];
    __syncthreads();

    // reduce partials + bias + bn2 + relu
    for (int o = tid; o < NSAMP * HDIM; o += 256) {
        int ns = o >> 5, h = o & 31;
        float u = 0.f;
#pragma unroll
        for (int w8 = 0; w8 < 8; ++w8) u += s_part[(w8 * NSAMP + ns) * 32 + h];
        u += w_l1_b[h];
        s_u[ns * HDIM + h] = fmaxf(fmaf(u, g_bn2s[h], g_bn2h[h]), 0.f);
    }
    __syncthreads();

    // layer-2 (32x32) -> pre-softmax logits
    for (int o = tid; o < NSAMP * HDIM; o += 256) {
        int ns = o >> 5, h = o & 31;
        float accl = w_l2_b[h];
        const float* w2row = &g_w2t[h * HDIM];
#pragma unroll
        for (int g = 0; g < 8; ++g) {
            float4 wv = *reinterpret_cast<const float4*>(&w2row[g * 4]);
            float4 bv = *reinterpret_cast<const float4*>(&s_u[ns * HDIM + g * 4]);
            accl = fmaf(bv.x, wv.x, accl);
            accl = fmaf(bv.y, wv.y, accl);
            accl = fmaf(bv.z, wv.z, accl);
            accl = fmaf(bv.w, wv.w, accl);
        }
        s_w[ns * 33 + h] = accl;
    }
    __syncthreads();

    // softmax over neighbors (warp 0, lane = h)
    if (warp == 0) {
        float m = -3.402823466e+38f;
#pragma unroll
        for (int ns = 0; ns < NSAMP; ++ns) m = fmaxf(m, s_w[ns * 33 + lane]);
        float ev[NSAMP], sum = 0.f;
#pragma unroll
        for (int ns = 0; ns < NSAMP; ++ns) { ev[ns] = __expf(s_w[ns * 33 + lane] - m); sum += ev[ns]; }
        float inv = 1.f / sum;
#pragma unroll
        for (int ns = 0; ns < NSAMP; ++ns) s_w[ns * 33 + lane] = ev[ns] * inv;
    }
    __syncthreads();

    // aggregation: out[c] = sum_ns w[ns][c&31] * (xv[idx[ns]][c] + pr[ns][c])
    {
        int i = tid & 31;
        float accl = 0.f;
#pragma unroll
        for (int ns = 0; ns < NSAMP; ++ns)
            accl = fmaf(s_w[ns * 33 + i], g_xv[s_idx[ns] * CIN + tid] + s_pr[ns * CIN + tid], accl);
        out[n * CIN + tid] = accl;
    }
}

// ---------------- launch ----------------
extern "C" void kernel_launch(void* const* d_in, const int* in_sizes, int n_in,
                              void* d_out, int out_size) {
    const float* p      = (const float*)d_in[0];
    const float* x      = (const float*)d_in[1];
    const float* w_q    = (const float*)d_in[2];
    const float* b_q    = (const float*)d_in[3];
    const float* w_k    = (const float*)d_in[4];
    const float* b_k    = (const float*)d_in[5];
    const float* w_v    = (const float*)d_in[6];
    const float* b_v    = (const float*)d_in[7];
    const float* p_w1   = (const float*)d_in[8];
    const float* p_b1   = (const float*)d_in[9];
    const float* p_bn_g = (const float*)d_in[10];
    const float* p_bn_b = (const float*)d_in[11];
    const float* p_bn_m = (const float*)d_in[12];
    const float* p_bn_v = (const float*)d_in[13];
    const float* p_w2   = (const float*)d_in[14];
    const float* p_b2   = (const float*)d_in[15];
    const float* bn1g   = (const float*)d_in[16];
    const float* bn1b   = (const float*)d_in[17];
    const float* bn1m   = (const float*)d_in[18];
    const float* bn1v   = (const float*)d_in[19];
    const float* w_l1_w = (const float*)d_in[20];
    const float* w_l1_b = (const float*)d_in[21];
    const float* bn2g   = (const float*)d_in[22];
    const float* bn2b   = (const float*)d_in[23];
    const float* bn2m   = (const float*)d_in[24];
    const float* bn2v   = (const float*)d_in[25];
    const float* w_l2_w = (const float*)d_in[26];
    const float* w_l2_b = (const float*)d_in[27];
    float* out = (float*)d_out;

    setup_kernel<<<32, 256>>>(p, w_l2_w, bn1g, bn1b, bn1m, bn1v, bn2g, bn2b, bn2m, bn2v);
    count_kernel<<<32, 256>>>();
    scan_scatter_kernel<<<1, CELLS>>>();
    knn_query<<<NPTS / 128, 128>>>();            // launch idx 3 -> ncu-captured
    qkv_gemm<<<dim3(CIN / 128, NPTS / 128, 3), 256>>>(x, w_q, b_q, w_k, b_k, w_v, b_v);
    fused_kernel<<<NPTS, 256>>>(p, p_w1, p_b1, p_bn_g, p_bn_b, p_bn_m, p_bn_v,
                                p_w2, p_b2, w_l1_w, w_l1_b, w_l2_b, out);
}

// round 8
// speedup vs baseline: 1.3778x; 1.3778x over previous
#include <cuda_runtime.h>

#define NPTS 8192
#define CIN  256
#define NSAMP 16
#define HDIM 32
#define GRES 8
#define CELLS (GRES * GRES * GRES)
#define CELLH 0.125f

// ---------------- scratch (device globals; no allocation) ----------------
__device__ float4 g_p4[NPTS];               // (x, y, z, |p|^2)
__device__ int    g_idx[NPTS * NSAMP];
__device__ float  g_xq[NPTS * CIN];
__device__ float  g_xk[NPTS * CIN];
__device__ float  g_xv[NPTS * CIN];
__device__ float  g_w2t[HDIM * HDIM];       // w_l2_w transposed: [h][k]
__device__ float  g_bn1s[CIN], g_bn1h[CIN];
__device__ float  g_bn2s[HDIM], g_bn2h[HDIM];
// grid structures
__device__ int    g_cellCnt[CELLS];         // counts, then reused as scatter cursor
__device__ int    g_cellStart[CELLS + 1];
__device__ float4 g_sp[NPTS];               // points sorted by cell
__device__ int    g_sidx[NPTS];             // original index of sorted point

__device__ __forceinline__ int cellCoord(float v) {
    int c = (int)(v * (float)GRES);
    return min(GRES - 1, max(0, c));
}

// ---------------- setup: pack points, zero cell counts, prep weights ----------------
__global__ void setup_kernel(const float* __restrict__ p,
                             const float* __restrict__ w_l2_w,
                             const float* __restrict__ g1, const float* __restrict__ b1,
                             const float* __restrict__ m1, const float* __restrict__ v1,
                             const float* __restrict__ g2, const float* __restrict__ b2,
                             const float* __restrict__ m2, const float* __restrict__ v2) {
    int i = blockIdx.x * 256 + threadIdx.x;
    if (i < NPTS) {
        float x = p[3 * i], y = p[3 * i + 1], z = p[3 * i + 2];
        g_p4[i] = make_float4(x, y, z, fmaf(z, z, fmaf(y, y, x * x)));
    }
    if (i < CELLS) g_cellCnt[i] = 0;
    if (blockIdx.x == 31) {
        int tid = threadIdx.x;
        for (int e = tid; e < HDIM * HDIM; e += 256) {
            int h = e >> 5, k = e & 31;
            g_w2t[e] = w_l2_w[k * HDIM + h];
        }
        if (tid < CIN) {
            float s = g1[tid] * rsqrtf(v1[tid] + 1e-5f);
            g_bn1s[tid] = s;
            g_bn1h[tid] = b1[tid] - m1[tid] * s;
        }
        if (tid < HDIM) {
            float s = g2[tid] * rsqrtf(v2[tid] + 1e-5f);
            g_bn2s[tid] = s;
            g_bn2h[tid] = b2[tid] - m2[tid] * s;
        }
    }
}

// ---------------- count points per cell ----------------
__global__ void count_kernel() {
    int i = blockIdx.x * 256 + threadIdx.x;
    if (i < NPTS) {
        float4 pt = g_p4[i];
        int c = cellCoord(pt.x) + (cellCoord(pt.y) << 3) + (cellCoord(pt.z) << 6);
        atomicAdd(&g_cellCnt[c], 1);
    }
}

// ---------------- single-block scan + scatter ----------------
__global__ __launch_bounds__(CELLS) void scan_scatter_kernel() {
    __shared__ int s[CELLS];
    int tid = threadIdx.x;
    int cnt = g_cellCnt[tid];
    s[tid] = cnt;
    __syncthreads();
    // Hillis-Steele inclusive scan
    for (int off = 1; off < CELLS; off <<= 1) {
        int v = 0;
        if (tid >= off) v = s[tid - off];
        __syncthreads();
        if (tid >= off) s[tid] += v;
        __syncthreads();
    }
    int start = s[tid] - cnt;
    g_cellStart[tid] = start;
    if (tid == CELLS - 1) g_cellStart[CELLS] = s[tid];
    g_cellCnt[tid] = start;     // reuse as cursor
    __syncthreads();
    // scatter (single block, grid-stride over points)
    for (int i = tid; i < NPTS; i += CELLS) {
        float4 pt = g_p4[i];
        int c = cellCoord(pt.x) + (cellCoord(pt.y) << 3) + (cellCoord(pt.z) << 6);
        int pos = atomicAdd(&g_cellCnt[c], 1);
        g_sp[pos] = pt;
        g_sidx[pos] = i;
    }
}

// ---------------- grid KNN query: WARP per query ----------------
// Exact top-16 by lexicographic (distance, index) == jax.lax.top_k(-d) semantics.
// Lanes partition each cell's candidates; per-lane sorted top-16 lists are
// merged by the 16-round warp argmin (also yields the global 16th-best for the
// shell-expansion bound — identical logic to the proven thread-per-query version).
__global__ __launch_bounds__(128) void knn_query() {
    __shared__ float md[4 * 512];        // 8KB
    __shared__ int   mi[4 * 512];        // 8KB

    int tid = threadIdx.x, lane = tid & 31, warp = tid >> 5;
    int t = blockIdx.x * 4 + warp;       // query (in sorted order)
    float4 qp = g_sp[t];
    int orig = g_sidx[t];
    float qx = qp.x, qy = qp.y, qz = qp.z, qsq = qp.w;
    int cx = cellCoord(qx), cy = cellCoord(qy), cz = cellCoord(qz);

    const float FINF = 3.402823466e+38f;
    float ld_[16];
    int   li_[16];
#pragma unroll
    for (int k = 0; k < 16; ++k) { ld_[k] = FINF; li_[k] = 0x7fffffff; }

#define SCAN_CELL(CX, CY, CZ)                                                   \
    {                                                                           \
        int cc = (CX) + ((CY) << 3) + ((CZ) << 6);                              \
        int s0 = g_cellStart[cc], s1 = g_cellStart[cc + 1];                     \
        for (int j = s0 + lane; j < s1; j += 32) {                              \
            float4 tp = g_sp[j];                                                \
            float dot = fmaf(qz, tp.z, fmaf(qy, tp.y, qx * tp.x));              \
            float d = fmaf(-2.f, dot, qsq + tp.w);                              \
            int idx = g_sidx[j];                                                \
            if (d < ld_[15] || (d == ld_[15] && idx < li_[15])) {               \
                ld_[15] = d; li_[15] = idx;                                     \
                _Pragma("unroll")                                               \
                for (int m = 15; m > 0; --m) {                                  \
                    bool sw = (ld_[m] < ld_[m - 1]) ||                          \
                              (ld_[m] == ld_[m - 1] && li_[m] < li_[m - 1]);    \
                    if (sw) {                                                   \
                        float td = ld_[m]; ld_[m] = ld_[m - 1]; ld_[m - 1] = td;\
                        int ti = li_[m]; li_[m] = li_[m - 1]; li_[m - 1] = ti;  \
                    }                                                           \
                }                                                               \
            }                                                                   \
        }                                                                       \
    }

    // initial box: Chebyshev distance <= 1
    {
        int z0 = max(0, cz - 1), z1 = min(GRES - 1, cz + 1);
        int y0 = max(0, cy - 1), y1 = min(GRES - 1, cy + 1);
        int x0 = max(0, cx - 1), x1 = min(GRES - 1, cx + 1);
        for (int z = z0; z <= z1; ++z)
            for (int y = y0; y <= y1; ++y)
                for (int x = x0; x <= x1; ++x)
                    SCAN_CELL(x, y, z)
    }

    int mb = warp * 512 + lane * 16;
    int R = 1;
    float myd = FINF; int myi = 0x7fffffff;   // lane r holds the r-th best

    while (true) {
        // ---- warp merge of per-lane sorted lists (lexicographic (d, idx)) ----
#pragma unroll
        for (int k = 0; k < 16; ++k) { md[mb + k] = ld_[k]; mi[mb + k] = li_[k]; }
        __syncwarp();

        int ptr = 0;
        float d16 = FINF;
        for (int r = 0; r < 16; ++r) {
            float bd; int bi;
            if (ptr < 16) { bd = md[mb + ptr]; bi = mi[mb + ptr]; }
            else          { bd = FINF;         bi = 0x7fffffff; }
            float vd = bd; int vi = bi;
#pragma unroll
            for (int off = 16; off; off >>= 1) {
                float od = __shfl_xor_sync(0xffffffffu, vd, off);
                int   oi = __shfl_xor_sync(0xffffffffu, vi, off);
                if (od < vd || (od == vd && oi < vi)) { vd = od; vi = oi; }
            }
            if (ptr < 16 && bd == vd && bi == vi) ptr++;
            if (lane == r) { myd = vd; myi = vi; }
            d16 = vd;    // after round 15: global 16th best (uniform across warp)
        }

        // ---- shell-expansion bound (identical to thread-per-query version) ----
        float rb = (float)R * CELLH;
        bool have16 = (d16 < FINF);
        if ((have16 && rb * rb > d16 * 1.00001f + 1e-6f) || R >= GRES) break;
        ++R;
        // process shell Chebyshev == R
        for (int dz = -R; dz <= R; ++dz) {
            int z = cz + dz;
            if (z < 0 || z > GRES - 1) continue;
            int adz = dz < 0 ? -dz : dz;
            for (int dy = -R; dy <= R; ++dy) {
                int y = cy + dy;
                if (y < 0 || y > GRES - 1) continue;
                int ady = dy < 0 ? -dy : dy;
                bool faceZY = (adz == R) || (ady == R);
                for (int dx = -R; dx <= R; ++dx) {
                    int x = cx + dx;
                    if (x < 0 || x > GRES - 1) continue;
                    int adx = dx < 0 ? -dx : dx;
                    if (!faceZY && adx != R) continue;
                    SCAN_CELL(x, y, z)
                }
            }
        }
    }
#undef SCAN_CELL

    if (lane < 16) g_idx[orig * NSAMP + lane] = myi;
}

// ---------------- QKV SGEMM: 128x128x8 tiles, 8x8/thread, double buffered ----------------
__global__ __launch_bounds__(256) void qkv_gemm(
    const float* __restrict__ x,
    const float* __restrict__ w_q, const float* __restrict__ b_q,
    const float* __restrict__ w_k, const float* __restrict__ b_k,
    const float* __restrict__ w_v, const float* __restrict__ b_v) {

    const int BM = 128, BN = 128, BK = 8, TM = 8, TN = 8;
    __shared__ float As[2][BK * BM];  // transposed
    __shared__ float Bs[2][BK * BN];

    const float* W; const float* bias; float* O;
    if (blockIdx.z == 0)      { W = w_q; bias = b_q; O = g_xq; }
    else if (blockIdx.z == 1) { W = w_k; bias = b_k; O = g_xk; }
    else                      { W = w_v; bias = b_v; O = g_xv; }

    int tid = threadIdx.x;
    int cRow = blockIdx.y, cCol = blockIdx.x;

    int innerRowA = tid >> 1, innerColA = tid & 1;          // 128 rows x 2 float4
    int innerRowB = tid >> 5, innerColB = tid & 31;         // 8 rows x 32 float4
    int threadCol = tid & 15, threadRow = tid >> 4;

    const float* Aptr = &x[(cRow * BM + innerRowA) * CIN + innerColA * 4];
    const float* Bptr = &W[innerRowB * CIN + cCol * BN + innerColB * 4];

    float acc[TM][TN];
#pragma unroll
    for (int i = 0; i < TM; ++i)
#pragma unroll
        for (int j = 0; j < TN; ++j) acc[i][j] = 0.f;

    float regM[TM], regN[TN];

    // prologue: tile 0 into buffer 0
    {
        float4 tA = *reinterpret_cast<const float4*>(Aptr);
        float4 tB = *reinterpret_cast<const float4*>(Bptr);
        As[0][(innerColA * 4 + 0) * BM + innerRowA] = tA.x;
        As[0][(innerColA * 4 + 1) * BM + innerRowA] = tA.y;
        As[0][(innerColA * 4 + 2) * BM + innerRowA] = tA.z;
        As[0][(innerColA * 4 + 3) * BM + innerRowA] = tA.w;
        *reinterpret_cast<float4*>(&Bs[0][innerRowB * BN + innerColB * 4]) = tB;
    }
    __syncthreads();

    int buf = 0;
#pragma unroll 2
    for (int k0 = 0; k0 < CIN - BK; k0 += BK) {
        float4 nA = *reinterpret_cast<const float4*>(Aptr + k0 + BK);
        float4 nB = *reinterpret_cast<const float4*>(Bptr + (k0 + BK) * CIN);

#pragma unroll
        for (int k = 0; k < BK; ++k) {
#pragma unroll
            for (int i = 0; i < TM; i += 4)
                *reinterpret_cast<float4*>(&regM[i]) =
                    *reinterpret_cast<float4*>(&As[buf][k * BM + threadRow * TM + i]);
#pragma unroll
            for (int j = 0; j < TN; j += 4)
                *reinterpret_cast<float4*>(&regN[j]) =
                    *reinterpret_cast<float4*>(&Bs[buf][k * BN + threadCol * TN + j]);
#pragma unroll
            for (int i = 0; i < TM; ++i)
#pragma unroll
                for (int j = 0; j < TN; ++j)
                    acc[i][j] = fmaf(regM[i], regN[j], acc[i][j]);
        }

        int nb = buf ^ 1;
        As[nb][(innerColA * 4 + 0) * BM + innerRowA] = nA.x;
        As[nb][(innerColA * 4 + 1) * BM + innerRowA] = nA.y;
        As[nb][(innerColA * 4 + 2) * BM + innerRowA] = nA.z;
        As[nb][(innerColA * 4 + 3) * BM + innerRowA] = nA.w;
        *reinterpret_cast<float4*>(&Bs[nb][innerRowB * BN + innerColB * 4]) = nB;
        __syncthreads();
        buf = nb;
    }

    // last tile
#pragma unroll
    for (int k = 0; k < BK; ++k) {
#pragma unroll
        for (int i = 0; i < TM; i += 4)
            *reinterpret_cast<float4*>(&regM[i]) =
                *reinterpret_cast<float4*>(&As[buf][k * BM + threadRow * TM + i]);
#pragma unroll
        for (int j = 0; j < TN; j += 4)
            *reinterpret_cast<float4*>(&regN[j]) =
                *reinterpret_cast<float4*>(&Bs[buf][k * BN + threadCol * TN + j]);
#pragma unroll
        for (int i = 0; i < TM; ++i)
#pragma unroll
            for (int j = 0; j < TN; ++j)
                acc[i][j] = fmaf(regM[i], regN[j], acc[i][j]);
    }

    int col0 = cCol * BN + threadCol * TN;
    float breg[TN];
#pragma unroll
    for (int j = 0; j < TN; ++j) breg[j] = bias[col0 + j];

#pragma unroll
    for (int i = 0; i < TM; ++i) {
        int row = cRow * BM + threadRow * TM + i;
        float4 v0 = make_float4(acc[i][0] + breg[0], acc[i][1] + breg[1],
                                acc[i][2] + breg[2], acc[i][3] + breg[3]);
        float4 v1 = make_float4(acc[i][4] + breg[4], acc[i][5] + breg[5],
                                acc[i][6] + breg[6], acc[i][7] + breg[7]);
        *reinterpret_cast<float4*>(&O[row * CIN + col0])     = v0;
        *reinterpret_cast<float4*>(&O[row * CIN + col0 + 4]) = v1;
    }
}

// ---------------- fused per-point kernel ----------------
__global__ __launch_bounds__(256) void fused_kernel(
    const float* __restrict__ p,
    const float* __restrict__ p_w1, const float* __restrict__ p_b1,
    const float* __restrict__ p_bn_g, const float* __restrict__ p_bn_b,
    const float* __restrict__ p_bn_m, const float* __restrict__ p_bn_v,
    const float* __restrict__ p_w2, const float* __restrict__ p_b2,
    const float* __restrict__ w_l1_w, const float* __restrict__ w_l1_b,
    const float* __restrict__ w_l2_b,
    float* __restrict__ out) {

    __shared__ float s_xq[CIN];             // 1 KB
    __shared__ float s_pr[NSAMP * CIN];     // 16 KB
    __shared__ float s_a[NSAMP * CIN];      // 16 KB (reused as partials)
    __shared__ float s_u[NSAMP * HDIM];     // 2 KB
    __shared__ float s_w[NSAMP * 33];       // padded
    __shared__ int   s_idx[NSAMP];
    __shared__ float s_tv[NSAMP][3];
    __shared__ float s_pn[3];

    int n = blockIdx.x, tid = threadIdx.x, lane = tid & 31, warp = tid >> 5;

    if (tid < NSAMP) s_idx[tid] = g_idx[n * NSAMP + tid];
    if (tid < 3)     s_pn[tid] = p[n * 3 + tid];
    s_xq[tid] = g_xq[n * CIN + tid];
    __syncthreads();

    // pr hidden: Linear(3,3) -> BN -> ReLU, one thread per neighbor
    if (tid < NSAMP) {
        int j = s_idx[tid];
        float dx = p[j * 3]     - s_pn[0];
        float dy = p[j * 3 + 1] - s_pn[1];
        float dz = p[j * 3 + 2] - s_pn[2];
#pragma unroll
        for (int k = 0; k < 3; ++k) {
            float h = dx * p_w1[k] + dy * p_w1[3 + k] + dz * p_w1[6 + k] + p_b1[k];
            h = (h - p_bn_m[k]) * rsqrtf(p_bn_v[k] + 1e-5f) * p_bn_g[k] + p_bn_b[k];
            s_tv[tid][k] = fmaxf(h, 0.f);
        }
    }
    __syncthreads();

    // pr full (3->256) + gather xk + bn1/relu into s_a
    {
        float b1s = g_bn1s[tid], b1h = g_bn1h[tid];
        float xqv = s_xq[tid];
        float w20 = p_w2[tid], w21 = p_w2[256 + tid], w22 = p_w2[512 + tid];
        float pb2 = p_b2[tid];
#pragma unroll
        for (int r = 0; r < NSAMP; ++r) {
            float prv = fmaf(s_tv[r][2], w22, fmaf(s_tv[r][1], w21, fmaf(s_tv[r][0], w20, pb2)));
            s_pr[r * CIN + tid] = prv;
            float rqk = g_xk[s_idx[r] * CIN + tid] - xqv + prv;
            s_a[r * CIN + tid] = fmaxf(fmaf(rqk, b1s, b1h), 0.f);
        }
    }
    __syncthreads();

    // layer-1 matvec: warp owns 32 input channels (c = warp*32..+31), lane = output h.
    // w_l1_w read in original [c][h] layout -> coalesced LDG across lanes.
    float acc[NSAMP];
#pragma unroll
    for (int ns = 0; ns < NSAMP; ++ns) acc[ns] = 0.f;
    {
        int cbase = warp * 32;
#pragma unroll
        for (int g = 0; g < 8; ++g) {
            int c0 = cbase + g * 4;
            float wa = w_l1_w[(c0 + 0) * HDIM + lane];
            float wb = w_l1_w[(c0 + 1) * HDIM + lane];
            float wc = w_l1_w[(c0 + 2) * HDIM + lane];
            float wd = w_l1_w[(c0 + 3) * HDIM + lane];
#pragma unroll
            for (int ns = 0; ns < NSAMP; ++ns) {
                float4 av = *reinterpret_cast<const float4*>(&s_a[ns * CIN + c0]);
                acc[ns] = fmaf(av.x, wa, acc[ns]);
                acc[ns] = fmaf(av.y, wb, acc[ns]);
                acc[ns] = fmaf(av.z, wc, acc[ns]);
                acc[ns] = fmaf(av.w, wd, acc[ns]);
            }
        }
    }
    __syncthreads();   // all reads of s_a done before reuse as partial buffer

    float* s_part = s_a;   // 8*16*32 = 4096 floats, fits exactly
#pragma unroll
    for (int ns = 0; ns < NSAMP; ++ns)
        s_part[(warp * NSAMP + ns) * 32 + lane] = acc[ns];
    __syncthreads();

    // reduce partials + bias + bn2 + relu
    for (int o = tid; o < NSAMP * HDIM; o += 256) {
        int ns = o >> 5, h = o & 31;
        float u = 0.f;
#pragma unroll
        for (int w8 = 0; w8 < 8; ++w8) u += s_part[(w8 * NSAMP + ns) * 32 + h];
        u += w_l1_b[h];
        s_u[ns * HDIM + h] = fmaxf(fmaf(u, g_bn2s[h], g_bn2h[h]), 0.f);
    }
    __syncthreads();

    // layer-2 (32x32) -> pre-softmax logits
    for (int o = tid; o < NSAMP * HDIM; o += 256) {
        int ns = o >> 5, h = o & 31;
        float accl = w_l2_b[h];
        const float* w2row = &g_w2t[h * HDIM];
#pragma unroll
        for (int g = 0; g < 8; ++g) {
            float4 wv = *reinterpret_cast<const float4*>(&w2row[g * 4]);
            float4 bv = *reinterpret_cast<const float4*>(&s_u[ns * HDIM + g * 4]);
            accl = fmaf(bv.x, wv.x, accl);
            accl = fmaf(bv.y, wv.y, accl);
            accl = fmaf(bv.z, wv.z, accl);
            accl = fmaf(bv.w, wv.w, accl);
        }
        s_w[ns * 33 + h] = accl;
    }
    __syncthreads();

    // softmax over neighbors (warp 0, lane = h)
    if (warp == 0) {
        float m = -3.402823466e+38f;
#pragma unroll
        for (int ns = 0; ns < NSAMP; ++ns) m = fmaxf(m, s_w[ns * 33 + lane]);
        float ev[NSAMP], sum = 0.f;
#pragma unroll
        for (int ns = 0; ns < NSAMP; ++ns) { ev[ns] = __expf(s_w[ns * 33 + lane] - m); sum += ev[ns]; }
        float inv = 1.f / sum;
#pragma unroll
        for (int ns = 0; ns < NSAMP; ++ns) s_w[ns * 33 + lane] = ev[ns] * inv;
    }
    __syncthreads();

    // aggregation: out[c] = sum_ns w[ns][c&31] * (xv[idx[ns]][c] + pr[ns][c])
    {
        int i = tid & 31;
        float accl = 0.f;
#pragma unroll
        for (int ns = 0; ns < NSAMP; ++ns)
            accl = fmaf(s_w[ns * 33 + i], g_xv[s_idx[ns] * CIN + tid] + s_pr[ns * CIN + tid], accl);
        out[n * CIN + tid] = accl;
    }
}

// ---------------- launch ----------------
extern "C" void kernel_launch(void* const* d_in, const int* in_sizes, int n_in,
                              void* d_out, int out_size) {
    const float* p      = (const float*)d_in[0];
    const float* x      = (const float*)d_in[1];
    const float* w_q    = (const float*)d_in[2];
    const float* b_q    = (const float*)d_in[3];
    const float* w_k    = (const float*)d_in[4];
    const float* b_k    = (const float*)d_in[5];
    const float* w_v    = (const float*)d_in[6];
    const float* b_v    = (const float*)d_in[7];
    const float* p_w1   = (const float*)d_in[8];
    const float* p_b1   = (const float*)d_in[9];
    const float* p_bn_g = (const float*)d_in[10];
    const float* p_bn_b = (const float*)d_in[11];
    const float* p_bn_m = (const float*)d_in[12];
    const float* p_bn_v = (const float*)d_in[13];
    const float* p_w2   = (const float*)d_in[14];
    const float* p_b2   = (const float*)d_in[15];
    const float* bn1g   = (const float*)d_in[16];
    const float* bn1b   = (const float*)d_in[17];
    const float* bn1m   = (const float*)d_in[18];
    const float* bn1v   = (const float*)d_in[19];
    const float* w_l1_w = (const float*)d_in[20];
    const float* w_l1_b = (const float*)d_in[21];
    const float* bn2g   = (const float*)d_in[22];
    const float* bn2b   = (const float*)d_in[23];
    const float* bn2m   = (const float*)d_in[24];
    const float* bn2v   = (const float*)d_in[25];
    const float* w_l2_w = (const float*)d_in[26];
    const float* w_l2_b = (const float*)d_in[27];
    float* out = (float*)d_out;

    setup_kernel<<<32, 256>>>(p, w_l2_w, bn1g, bn1b, bn1m, bn1v, bn2g, bn2b, bn2m, bn2v);
    count_kernel<<<32, 256>>>();
    scan_scatter_kernel<<<1, CELLS>>>();
    knn_query<<<NPTS / 4, 128>>>();              // launch idx 3 -> ncu-captured
    qkv_gemm<<<dim3(CIN / 128, NPTS / 128, 3), 256>>>(x, w_q, b_q, w_k, b_k, w_v, b_v);
    fused_kernel<<<NPTS, 256>>>(p, p_w1, p_b1, p_bn_g, p_bn_b, p_bn_m, p_bn_v,
                                p_w2, p_b2, w_l1_w, w_l1_b, w_l2_b, out);
}